// round 1
// baseline (speedup 1.0000x reference)
#include <cuda_runtime.h>
#include <cuda_fp16.h>

#define N      8192
#define NX     32
#define NY     16
#define NZ     16
#define NUM_ITER 5
#define INV2A2 0.02f   // 1/(2*ALPHA^2), ALPHA=5
#define INV2G2 0.02f   // 1/(2*GAMMA^2), GAMMA=5
#define INVB   0.2f    // 1/BETA, BETA=5
#define W_1F   1.0f
#define W_2F   1.0f
#define D2MAX  1412    // 31^2+15^2+15^2 = 1411 max index

// Scratch (device globals; allocation-free per harness rules)
__device__ float4 g_pt[N];            // u1, u2, g, 0
__device__ float4 g_pt2[N];           // u1, u2, m1*g, m2
__device__ float  g_r1[N];            // bilateral row sums
__device__ __half g_M[(size_t)N * N]; // combined filter matrix, 128MB fp16
__device__ float4 g_lu[N];            // logits interleaved [N][4]
__device__ float4 g_q[N];             // current q [N][4]
__device__ float4 g_qcomb[N];         // filter output accumulator [N][4]

__device__ __forceinline__ float4 softmax4(float4 l) {
    float m = fmaxf(fmaxf(l.x, l.y), fmaxf(l.z, l.w));
    float e0 = __expf(l.x - m), e1 = __expf(l.y - m);
    float e2 = __expf(l.z - m), e3 = __expf(l.w - m);
    float s = 1.0f / (e0 + e1 + e2 + e3);
    return make_float4(e0 * s, e1 * s, e2 * s, e3 * s);
}

// P0: per-point features, logit reorg, initial q = softmax(lu), zero accumulators
__global__ void p0_kernel(const float* __restrict__ lu, const float* __restrict__ feat) {
    int i = blockIdx.x * blockDim.x + threadIdx.x;
    if (i >= N) return;
    float u1 = feat[i] * INVB, u2 = feat[N + i] * INVB;
    float g = __expf(-0.5f * (u1 * u1 + u2 * u2));
    g_pt[i] = make_float4(u1, u2, g, 0.f);
    float4 l = make_float4(lu[i], lu[N + i], lu[2 * N + i], lu[3 * N + i]);
    g_lu[i] = l;
    g_q[i] = softmax4(l);
    g_qcomb[i] = make_float4(0.f, 0.f, 0.f, 0.f);
}

// P1: bilateral kernel row sums r1_i = g_i * sum_j Sa[D2] * g_j * exp(u_i . u_j)
// 1024 blocks x 256 threads; each block owns 8 rows (one per warp), scans all j.
__global__ void p1_kernel() {
    __shared__ float  Sa[D2MAX];
    __shared__ float4 tile[256];
    int tid = threadIdx.x;
    for (int t = tid; t < D2MAX; t += 256) Sa[t] = __expf(-INV2A2 * (float)t);
    int warp = tid >> 5, lane = tid & 31;
    int i = blockIdx.x * 8 + warp;
    float4 pi = g_pt[i];
    int xi = i >> 8, yi = (i >> 4) & 15, zi = i & 15;
    float acc = 0.f;
    for (int jb = 0; jb < N; jb += 256) {
        __syncthreads();                 // protects prior tile reads + first-pass table fill
        tile[tid] = g_pt[jb + tid];
        __syncthreads();
        #pragma unroll 4
        for (int t = lane; t < 256; t += 32) {
            int j = jb + t;
            int dx = xi - (j >> 8), dy = yi - ((j >> 4) & 15), dz = zi - (j & 15);
            int D2 = dx * dx + dy * dy + dz * dz;
            float4 pj = tile[t];
            acc += Sa[D2] * pj.z * __expf(pi.x * pj.x + pi.y * pj.y);
        }
    }
    #pragma unroll
    for (int o = 16; o > 0; o >>= 1) acc += __shfl_xor_sync(0xffffffffu, acc, o);
    if (lane == 0) g_r1[i] = pi.z * acc;
}

// P1b: analytic spatial-kernel row sums (separable), build scaled point data
__global__ void p1b_kernel() {
    int i = blockIdx.x * blockDim.x + threadIdx.x;
    if (i >= N) return;
    int x = i >> 8, y = (i >> 4) & 15, z = i & 15;
    float Rx = 0.f, Ry = 0.f, Rz = 0.f;
    for (int t = 0; t < NX; t++) { int d = x - t; Rx += __expf(-INV2G2 * (float)(d * d)); }
    for (int t = 0; t < NY; t++) { int d = y - t; Ry += __expf(-INV2G2 * (float)(d * d)); }
    for (int t = 0; t < NZ; t++) { int d = z - t; Rz += __expf(-INV2G2 * (float)(d * d)); }
    float m1 = sqrtf(W_1F) * rsqrtf(g_r1[i]);
    float m2 = sqrtf(W_2F) * rsqrtf(Rx * Ry * Rz);
    float4 p = g_pt[i];
    g_pt2[i] = make_float4(p.x, p.y, m1 * p.z, m2);
}

// P2: materialize combined M in fp16. 1024 blocks x 256; block = 8 rows, warp per row,
// lane writes 8 consecutive j as one uint4.
__global__ void p2_kernel() {
    __shared__ float  Sa[D2MAX];
    __shared__ float  Sg[D2MAX];
    __shared__ float4 tile[256];
    int tid = threadIdx.x;
    for (int t = tid; t < D2MAX; t += 256) {
        float v = (float)t;
        Sa[t] = __expf(-INV2A2 * v);
        Sg[t] = __expf(-INV2G2 * v);
    }
    int warp = tid >> 5, lane = tid & 31;
    int i = blockIdx.x * 8 + warp;
    float4 pi = g_pt2[i];
    int xi = i >> 8, yi = (i >> 4) & 15, zi = i & 15;
    __half* row = g_M + (size_t)i * N;
    for (int jb = 0; jb < N; jb += 256) {
        __syncthreads();
        tile[tid] = g_pt2[jb + tid];
        __syncthreads();
        int t0 = lane * 8;
        float v[8];
        #pragma unroll
        for (int k = 0; k < 8; k++) {
            int t = t0 + k;
            int j = jb + t;
            int dx = xi - (j >> 8), dy = yi - ((j >> 4) & 15), dz = zi - (j & 15);
            int D2 = dx * dx + dy * dy + dz * dz;
            float4 pj = tile[t];
            float e = __expf(pi.x * pj.x + pi.y * pj.y);
            v[k] = pi.z * pj.z * Sa[D2] * e + pi.w * pj.w * Sg[D2];
        }
        union { uint4 u; __half2 h[4]; } pk;
        pk.h[0] = __floats2half2_rn(v[0], v[1]);
        pk.h[1] = __floats2half2_rn(v[2], v[3]);
        pk.h[2] = __floats2half2_rn(v[4], v[5]);
        pk.h[3] = __floats2half2_rn(v[6], v[7]);
        *reinterpret_cast<uint4*>(row + jb + t0) = pk.u;
    }
}

// G: q_comb = M @ q  (M symmetric, so read columns as rows).
// grid (8 i-supers, 32 j-chunks) x 256 threads. Warp owns 128 consecutive output
// rows; lane holds 4 rows. Per j: uint2 (4 fp16) coalesced load + broadcast q[j].
#define JT 256
__global__ void g_kernel() {
    __shared__ float4 qsh[JT];
    int tid = threadIdx.x, warp = tid >> 5, lane = tid & 31;
    int jb = blockIdx.y * JT;
    for (int t = tid; t < JT; t += 256) qsh[t] = g_q[jb + t];
    __syncthreads();
    int i0 = blockIdx.x * 1024 + warp * 128 + lane * 4;
    float4 a0 = make_float4(0.f, 0.f, 0.f, 0.f), a1 = a0, a2 = a0, a3 = a0;
    const __half* Mp = g_M + (size_t)jb * N + i0;
    #pragma unroll 4
    for (int jj = 0; jj < JT; jj++) {
        float4 q4 = qsh[jj];
        uint2 raw = *reinterpret_cast<const uint2*>(Mp + (size_t)jj * N);
        __half2 h01 = *reinterpret_cast<__half2*>(&raw.x);
        __half2 h23 = *reinterpret_cast<__half2*>(&raw.y);
        float2 m01 = __half22float2(h01);
        float2 m23 = __half22float2(h23);
        a0.x += m01.x * q4.x; a0.y += m01.x * q4.y; a0.z += m01.x * q4.z; a0.w += m01.x * q4.w;
        a1.x += m01.y * q4.x; a1.y += m01.y * q4.y; a1.z += m01.y * q4.z; a1.w += m01.y * q4.w;
        a2.x += m23.x * q4.x; a2.y += m23.x * q4.y; a2.z += m23.x * q4.z; a2.w += m23.x * q4.w;
        a3.x += m23.y * q4.x; a3.y += m23.y * q4.y; a3.z += m23.y * q4.z; a3.w += m23.y * q4.w;
    }
    float* b0 = reinterpret_cast<float*>(&g_qcomb[i0]);
    atomicAdd(b0 + 0, a0.x);  atomicAdd(b0 + 1, a0.y);  atomicAdd(b0 + 2, a0.z);  atomicAdd(b0 + 3, a0.w);
    atomicAdd(b0 + 4, a1.x);  atomicAdd(b0 + 5, a1.y);  atomicAdd(b0 + 6, a1.z);  atomicAdd(b0 + 7, a1.w);
    atomicAdd(b0 + 8, a2.x);  atomicAdd(b0 + 9, a2.y);  atomicAdd(b0 + 10, a2.z); atomicAdd(b0 + 11, a2.w);
    atomicAdd(b0 + 12, a3.x); atomicAdd(b0 + 13, a3.y); atomicAdd(b0 + 14, a3.z); atomicAdd(b0 + 15, a3.w);
}

// S: compatibility transform + softmax update; zeroes accumulator for next iter;
// writes planar output on the last iteration.
__global__ void s_kernel(const float* __restrict__ W, float* __restrict__ out, int last) {
    int i = blockIdx.x * blockDim.x + threadIdx.x;
    if (i >= N) return;
    float4 qc = g_qcomb[i];
    float w[16];
    #pragma unroll
    for (int k = 0; k < 16; k++) w[k] = W[k];
    float4 l = g_lu[i];
    l.x -= w[0]  * qc.x + w[1]  * qc.y + w[2]  * qc.z + w[3]  * qc.w;
    l.y -= w[4]  * qc.x + w[5]  * qc.y + w[6]  * qc.z + w[7]  * qc.w;
    l.z -= w[8]  * qc.x + w[9]  * qc.y + w[10] * qc.z + w[11] * qc.w;
    l.w -= w[12] * qc.x + w[13] * qc.y + w[14] * qc.z + w[15] * qc.w;
    float4 q = softmax4(l);
    g_q[i] = q;
    g_qcomb[i] = make_float4(0.f, 0.f, 0.f, 0.f);
    if (last) {
        out[i]         = q.x;
        out[N + i]     = q.y;
        out[2 * N + i] = q.z;
        out[3 * N + i] = q.w;
    }
}

extern "C" void kernel_launch(void* const* d_in, const int* in_sizes, int n_in,
                              void* d_out, int out_size) {
    const float* lu   = (const float*)d_in[0];
    const float* feat = (const float*)d_in[1];
    const float* comp = (const float*)d_in[2];
    float* out = (float*)d_out;

    p0_kernel<<<32, 256>>>(lu, feat);
    p1_kernel<<<1024, 256>>>();
    p1b_kernel<<<32, 256>>>();
    p2_kernel<<<1024, 256>>>();
    for (int it = 0; it < NUM_ITER; ++it) {
        g_kernel<<<dim3(8, 32), 256>>>();
        s_kernel<<<32, 256>>>(comp, out, it == NUM_ITER - 1 ? 1 : 0);
    }
}

// round 2
// speedup vs baseline: 2.1750x; 2.1750x over previous
#include <cuda_runtime.h>
#include <cuda_fp16.h>

#define N      8192
#define NX     32
#define NY     16
#define NZ     16
#define NUM_ITER 5
#define INV2A2 0.02f   // 1/(2*ALPHA^2), ALPHA=5
#define INV2G2 0.02f   // 1/(2*GAMMA^2), GAMMA=5
#define INVB   0.2f    // 1/BETA, BETA=5
#define W_1F   1.0f
#define W_2F   1.0f

// Scratch (device globals; allocation-free per harness rules)
__device__ float4 g_pt[N];            // u1, u2, g, 0
__device__ float4 g_pt2[N];           // u1, u2, m1*g, m2
__device__ float  g_r1[N];            // bilateral row sums
__device__ __half g_M[(size_t)N * N]; // combined filter matrix, 128MB fp16
__device__ float4 g_lu[N];            // logits interleaved [N][4]
__device__ float4 g_q[N];             // current q [N][4]
__device__ float4 g_qcomb[N];         // filter output accumulator [N][4]

__device__ __forceinline__ float4 softmax4(float4 l) {
    float m = fmaxf(fmaxf(l.x, l.y), fmaxf(l.z, l.w));
    float e0 = __expf(l.x - m), e1 = __expf(l.y - m);
    float e2 = __expf(l.z - m), e3 = __expf(l.w - m);
    float s = 1.0f / (e0 + e1 + e2 + e3);
    return make_float4(e0 * s, e1 * s, e2 * s, e3 * s);
}

// P0: per-point features, logit reorg, initial q = softmax(lu), zero accumulators
__global__ void p0_kernel(const float* __restrict__ lu, const float* __restrict__ feat) {
    int i = blockIdx.x * blockDim.x + threadIdx.x;
    if (i >= N) return;
    float u1 = feat[i] * INVB, u2 = feat[N + i] * INVB;
    float g = __expf(-0.5f * (u1 * u1 + u2 * u2));
    g_pt[i] = make_float4(u1, u2, g, 0.f);
    float4 l = make_float4(lu[i], lu[N + i], lu[2 * N + i], lu[3 * N + i]);
    g_lu[i] = l;
    g_q[i] = softmax4(l);
    g_qcomb[i] = make_float4(0.f, 0.f, 0.f, 0.f);
}

// P1: bilateral row sums  r1_i = g_i * sum_j g_j * exp(u_i.u_j - D2/50)
// 1024 blocks x 256 threads; warp per row, lanes strided (conflict-free LDS),
// exp fused (no tables). For j = jb+lane+32k: z,x const per tile, dy linear in k.
__global__ void p1_kernel() {
    __shared__ float4 tile[256];
    int tid = threadIdx.x;
    int warp = tid >> 5, lane = tid & 31;
    int i = blockIdx.x * 8 + warp;
    float4 pi = g_pt[i];
    int xi = i >> 8, yi = (i >> 4) & 15, zi = i & 15;
    int lh = lane >> 4;                  // y sub-offset of this lane
    float dz = (float)(zi - (lane & 15));
    float dzq = dz * dz;
    float dy0 = (float)(yi - lh);        // dy for k=0; decreases by 2 per k
    float acc = 0.f;
    for (int jb = 0; jb < N; jb += 256) {
        __syncthreads();
        tile[tid] = g_pt[jb + tid];
        __syncthreads();
        int dx = xi - (jb >> 8);
        float basef = (float)(dx * dx) + dzq;
        #pragma unroll
        for (int k = 0; k < 8; k++) {
            float4 pj = tile[lane + 32 * k];
            float dy = dy0 - 2.0f * (float)k;
            float D2f = fmaf(dy, dy, basef);
            float dot = fmaf(pi.x, pj.x, pi.y * pj.y);
            acc += pj.z * __expf(fmaf(-INV2A2, D2f, dot));
        }
    }
    #pragma unroll
    for (int o = 16; o > 0; o >>= 1) acc += __shfl_xor_sync(0xffffffffu, acc, o);
    if (lane == 0) g_r1[i] = pi.z * acc;
}

// P1b: analytic spatial-kernel row sums (separable), build scaled point data
__global__ void p1b_kernel() {
    int i = blockIdx.x * blockDim.x + threadIdx.x;
    if (i >= N) return;
    int x = i >> 8, y = (i >> 4) & 15, z = i & 15;
    float Rx = 0.f, Ry = 0.f, Rz = 0.f;
    for (int t = 0; t < NX; t++) { int d = x - t; Rx += __expf(-INV2G2 * (float)(d * d)); }
    for (int t = 0; t < NY; t++) { int d = y - t; Ry += __expf(-INV2G2 * (float)(d * d)); }
    for (int t = 0; t < NZ; t++) { int d = z - t; Rz += __expf(-INV2G2 * (float)(d * d)); }
    float m1 = sqrtf(W_1F) * rsqrtf(g_r1[i]);
    float m2 = sqrtf(W_2F) * rsqrtf(Rx * Ry * Rz);
    float4 p = g_pt[i];
    g_pt2[i] = make_float4(p.x, p.y, m1 * p.z, m2);
}

// P2: materialize combined M in fp16. Warp per row, lanes STRIDED (conflict-free),
// exp fused (no tables). Per k, warp stores 32 consecutive halfs (64B coalesced).
__global__ void p2_kernel() {
    __shared__ float4 tile[256];
    int tid = threadIdx.x;
    int warp = tid >> 5, lane = tid & 31;
    int i = blockIdx.x * 8 + warp;
    float4 pi = g_pt2[i];
    int xi = i >> 8, yi = (i >> 4) & 15, zi = i & 15;
    int lh = lane >> 4;
    float dz = (float)(zi - (lane & 15));
    float dzq = dz * dz;
    float dy0 = (float)(yi - lh);
    __half* row = g_M + (size_t)i * N;
    for (int jb = 0; jb < N; jb += 256) {
        __syncthreads();
        tile[tid] = g_pt2[jb + tid];
        __syncthreads();
        int dx = xi - (jb >> 8);
        float basef = (float)(dx * dx) + dzq;
        #pragma unroll
        for (int k = 0; k < 8; k++) {
            int t = lane + 32 * k;
            float4 pj = tile[t];
            float dy = dy0 - 2.0f * (float)k;
            float D2f = fmaf(dy, dy, basef);
            float dot = fmaf(pi.x, pj.x, pi.y * pj.y);
            float e1 = __expf(fmaf(-INV2A2, D2f, dot));   // bilateral (incl. spatial factor)
            float e2 = __expf(-INV2G2 * D2f);             // pure spatial
            float v = fmaf(pi.z * pj.z, e1, pi.w * pj.w * e2);
            row[jb + t] = __float2half_rn(v);
        }
    }
}

// G: q_comb = M @ q  (M symmetric, read columns as rows).
// grid (8 i-supers, 64 j-chunks) x 256. Warp owns 128 consecutive output rows;
// lane holds 4 rows (uint2 coalesced load). q[j] broadcast from shared.
#define JT 128
__global__ void g_kernel() {
    __shared__ float4 qsh[JT];
    int tid = threadIdx.x, warp = tid >> 5, lane = tid & 31;
    int jb = blockIdx.y * JT;
    if (tid < JT) qsh[tid] = g_q[jb + tid];
    __syncthreads();
    int i0 = blockIdx.x * 1024 + warp * 128 + lane * 4;
    float4 a0 = make_float4(0.f, 0.f, 0.f, 0.f), a1 = a0, a2 = a0, a3 = a0;
    const __half* Mp = g_M + (size_t)jb * N + i0;
    #pragma unroll 8
    for (int jj = 0; jj < JT; jj++) {
        float4 q4 = qsh[jj];
        uint2 raw = *reinterpret_cast<const uint2*>(Mp + (size_t)jj * N);
        __half2 h01 = *reinterpret_cast<__half2*>(&raw.x);
        __half2 h23 = *reinterpret_cast<__half2*>(&raw.y);
        float2 m01 = __half22float2(h01);
        float2 m23 = __half22float2(h23);
        a0.x += m01.x * q4.x; a0.y += m01.x * q4.y; a0.z += m01.x * q4.z; a0.w += m01.x * q4.w;
        a1.x += m01.y * q4.x; a1.y += m01.y * q4.y; a1.z += m01.y * q4.z; a1.w += m01.y * q4.w;
        a2.x += m23.x * q4.x; a2.y += m23.x * q4.y; a2.z += m23.x * q4.z; a2.w += m23.x * q4.w;
        a3.x += m23.y * q4.x; a3.y += m23.y * q4.y; a3.z += m23.y * q4.z; a3.w += m23.y * q4.w;
    }
    float* b0 = reinterpret_cast<float*>(&g_qcomb[i0]);
    atomicAdd(b0 + 0, a0.x);  atomicAdd(b0 + 1, a0.y);  atomicAdd(b0 + 2, a0.z);  atomicAdd(b0 + 3, a0.w);
    atomicAdd(b0 + 4, a1.x);  atomicAdd(b0 + 5, a1.y);  atomicAdd(b0 + 6, a1.z);  atomicAdd(b0 + 7, a1.w);
    atomicAdd(b0 + 8, a2.x);  atomicAdd(b0 + 9, a2.y);  atomicAdd(b0 + 10, a2.z); atomicAdd(b0 + 11, a2.w);
    atomicAdd(b0 + 12, a3.x); atomicAdd(b0 + 13, a3.y); atomicAdd(b0 + 14, a3.z); atomicAdd(b0 + 15, a3.w);
}

// S: compatibility transform + softmax update; zeroes accumulator for next iter;
// writes planar output on the last iteration.
__global__ void s_kernel(const float* __restrict__ W, float* __restrict__ out, int last) {
    int i = blockIdx.x * blockDim.x + threadIdx.x;
    if (i >= N) return;
    float4 qc = g_qcomb[i];
    float w[16];
    #pragma unroll
    for (int k = 0; k < 16; k++) w[k] = W[k];
    float4 l = g_lu[i];
    l.x -= w[0]  * qc.x + w[1]  * qc.y + w[2]  * qc.z + w[3]  * qc.w;
    l.y -= w[4]  * qc.x + w[5]  * qc.y + w[6]  * qc.z + w[7]  * qc.w;
    l.z -= w[8]  * qc.x + w[9]  * qc.y + w[10] * qc.z + w[11] * qc.w;
    l.w -= w[12] * qc.x + w[13] * qc.y + w[14] * qc.z + w[15] * qc.w;
    float4 q = softmax4(l);
    g_q[i] = q;
    g_qcomb[i] = make_float4(0.f, 0.f, 0.f, 0.f);
    if (last) {
        out[i]         = q.x;
        out[N + i]     = q.y;
        out[2 * N + i] = q.z;
        out[3 * N + i] = q.w;
    }
}

extern "C" void kernel_launch(void* const* d_in, const int* in_sizes, int n_in,
                              void* d_out, int out_size) {
    const float* lu   = (const float*)d_in[0];
    const float* feat = (const float*)d_in[1];
    const float* comp = (const float*)d_in[2];
    float* out = (float*)d_out;

    p0_kernel<<<32, 256>>>(lu, feat);
    p1_kernel<<<1024, 256>>>();
    p1b_kernel<<<32, 256>>>();
    p2_kernel<<<1024, 256>>>();
    for (int it = 0; it < NUM_ITER; ++it) {
        g_kernel<<<dim3(8, 64), 256>>>();
        s_kernel<<<32, 256>>>(comp, out, it == NUM_ITER - 1 ? 1 : 0);
    }
}

// round 3
// speedup vs baseline: 3.6161x; 1.6625x over previous
#include <cuda_runtime.h>
#include <cuda_fp16.h>

#define N      8192
#define NX     32
#define NY     16
#define NZ     16
#define NUM_ITER 5
#define INV2A2 0.02f   // 1/(2*ALPHA^2), ALPHA=5
#define INV2G2 0.02f   // 1/(2*GAMMA^2), GAMMA=5
#define INVB   0.2f    // 1/BETA, BETA=5
#define NCHUNK 64      // j-chunks in g (JT = N / NCHUNK)
#define JT     128

// Scratch (device globals; allocation-free per harness rules)
__device__ float4 g_pt[N];                    // u1, u2, g, 0
__device__ float  g_r1[N];                    // bilateral row sums (from p2)
__device__ float2 g_m12[N];                   // m1, m2
__device__ __half g_B[(size_t)N * N];         // UNscaled bilateral matrix, 128MB fp16
__device__ float4 g_lu[N];                    // logits interleaved [N][4]
__device__ float4 g_v1[N];                    // m1 ⊙ q
__device__ float4 g_v2[N];                    // m2 ⊙ q
__device__ float4 g_part[NCHUNK * N];         // g partial sums [chunk][i][4]
__device__ float4 g_t1[N];                    // spatial tmp after x+y passes

__device__ __forceinline__ float4 softmax4(float4 l) {
    float m = fmaxf(fmaxf(l.x, l.y), fmaxf(l.z, l.w));
    float e0 = __expf(l.x - m), e1 = __expf(l.y - m);
    float e2 = __expf(l.z - m), e3 = __expf(l.w - m);
    float s = 1.0f / (e0 + e1 + e2 + e3);
    return make_float4(e0 * s, e1 * s, e2 * s, e3 * s);
}

// P0: per-point features + logit reorg
__global__ void p0_kernel(const float* __restrict__ lu, const float* __restrict__ feat) {
    int i = blockIdx.x * blockDim.x + threadIdx.x;
    if (i >= N) return;
    float u1 = feat[i] * INVB, u2 = feat[N + i] * INVB;
    float g = __expf(-0.5f * (u1 * u1 + u2 * u2));
    g_pt[i] = make_float4(u1, u2, g, 0.f);
    g_lu[i] = make_float4(lu[i], lu[N + i], lu[2 * N + i], lu[3 * N + i]);
}

// P2: materialize UNscaled bilateral B_ij = g_i g_j exp(u_i.u_j - D2/50), fp16,
// accumulating row sums on the fly (replaces old p1). Warp per row, lanes strided.
__global__ void p2_kernel() {
    __shared__ float4 tile[256];
    int tid = threadIdx.x;
    int warp = tid >> 5, lane = tid & 31;
    int i = blockIdx.x * 8 + warp;
    float4 pi = g_pt[i];
    int xi = i >> 8, yi = (i >> 4) & 15, zi = i & 15;
    float dz = (float)(zi - (lane & 15));
    float dzq = dz * dz;
    float dy0 = (float)(yi - (lane >> 4));
    __half* row = g_B + (size_t)i * N;
    float rsum = 0.f;
    for (int jb = 0; jb < N; jb += 256) {
        __syncthreads();
        tile[tid] = g_pt[jb + tid];
        __syncthreads();
        int dx = xi - (jb >> 8);
        float basef = (float)(dx * dx) + dzq;
        #pragma unroll
        for (int k = 0; k < 8; k++) {
            int t = lane + 32 * k;
            float4 pj = tile[t];
            float dy = dy0 - 2.0f * (float)k;
            float D2f = fmaf(dy, dy, basef);
            float dot = fmaf(pi.x, pj.x, pi.y * pj.y);
            float v = pi.z * pj.z * __expf(fmaf(-INV2A2, D2f, dot));
            rsum += v;
            row[jb + t] = __float2half_rn(v);
        }
    }
    #pragma unroll
    for (int o = 16; o > 0; o >>= 1) rsum += __shfl_xor_sync(0xffffffffu, rsum, o);
    if (lane == 0) g_r1[i] = rsum;
}

// P1b: scales (bilateral from r1; spatial analytic separable) + initial scaled q
__global__ void p1b_kernel() {
    int i = blockIdx.x * blockDim.x + threadIdx.x;
    if (i >= N) return;
    int x = i >> 8, y = (i >> 4) & 15, z = i & 15;
    float Rx = 0.f, Ry = 0.f, Rz = 0.f;
    for (int t = 0; t < NX; t++) { int d = x - t; Rx += __expf(-INV2G2 * (float)(d * d)); }
    for (int t = 0; t < NY; t++) { int d = y - t; Ry += __expf(-INV2G2 * (float)(d * d)); }
    for (int t = 0; t < NZ; t++) { int d = z - t; Rz += __expf(-INV2G2 * (float)(d * d)); }
    float m1 = rsqrtf(g_r1[i]);
    float m2 = rsqrtf(Rx * Ry * Rz);
    g_m12[i] = make_float2(m1, m2);
    float4 q = softmax4(g_lu[i]);
    g_v1[i] = make_float4(q.x * m1, q.y * m1, q.z * m1, q.w * m1);
    g_v2[i] = make_float4(q.x * m2, q.y * m2, q.z * m2, q.w * m2);
}

// G: partial = B(cols) @ v1 over one j-chunk. B symmetric -> read columns as rows.
// grid (4, 64) x 256. Warp owns 256 consecutive i (lane*8, uint4 = 16B/lane/j).
// No atomics: partials to g_part[chunk], reduced in szs_kernel.
__global__ void g_kernel() {
    __shared__ float4 qsh[JT];
    int tid = threadIdx.x, warp = tid >> 5, lane = tid & 31;
    int jb = blockIdx.y * JT;
    if (tid < JT) qsh[tid] = g_v1[jb + tid];
    __syncthreads();
    int i0 = blockIdx.x * 2048 + warp * 256 + lane * 8;
    float4 a[8];
    #pragma unroll
    for (int k = 0; k < 8; k++) a[k] = make_float4(0.f, 0.f, 0.f, 0.f);
    const __half* Bp = g_B + (size_t)jb * N + i0;
    #pragma unroll 8
    for (int jj = 0; jj < JT; jj++) {
        float4 q4 = qsh[jj];
        uint4 raw = *reinterpret_cast<const uint4*>(Bp + (size_t)jj * N);
        const __half2* hp = reinterpret_cast<const __half2*>(&raw);
        #pragma unroll
        for (int p = 0; p < 4; p++) {
            float2 m = __half22float2(hp[p]);
            a[2*p].x   += m.x * q4.x; a[2*p].y   += m.x * q4.y;
            a[2*p].z   += m.x * q4.z; a[2*p].w   += m.x * q4.w;
            a[2*p+1].x += m.y * q4.x; a[2*p+1].y += m.y * q4.y;
            a[2*p+1].z += m.y * q4.z; a[2*p+1].w += m.y * q4.w;
        }
    }
    float4* dst = g_part + (size_t)blockIdx.y * N + i0;
    #pragma unroll
    for (int k = 0; k < 8; k++) dst[k] = a[k];
}

// SXY: spatial separable passes along x then y, per z-slice block.
__global__ void sxy_kernel() {
    __shared__ float4 sin_[512];
    __shared__ float4 smid[512];
    __shared__ float gx[NX];
    int z = blockIdx.x, tid = threadIdx.x;
    if (tid < NX) gx[tid] = __expf(-INV2G2 * (float)(tid * tid));
    int x = tid >> 4, y = tid & 15;
    sin_[tid] = g_v2[x * 256 + y * 16 + z];
    __syncthreads();
    float4 acc = make_float4(0.f, 0.f, 0.f, 0.f);
    for (int xp = 0; xp < NX; xp++) {
        int d = x - xp; if (d < 0) d = -d;
        float w = gx[d];
        float4 v = sin_[xp * 16 + y];
        acc.x += w * v.x; acc.y += w * v.y; acc.z += w * v.z; acc.w += w * v.w;
    }
    smid[tid] = acc;
    __syncthreads();
    float4 acc2 = make_float4(0.f, 0.f, 0.f, 0.f);
    for (int yp = 0; yp < NY; yp++) {
        int d = y - yp; if (d < 0) d = -d;
        float w = gx[d];
        float4 v = smid[x * 16 + yp];
        acc2.x += w * v.x; acc2.y += w * v.y; acc2.z += w * v.z; acc2.w += w * v.w;
    }
    g_t1[x * 256 + y * 16 + z] = acc2;
}

// SZS: z-pass of spatial + reduce bilateral partials + compat + softmax update.
// grid 32 (x-slab) x 256 threads (one per (y,z)).
__global__ void szs_kernel(const float* __restrict__ W, float* __restrict__ out, int last) {
    __shared__ float4 st[256];
    __shared__ float gz[NZ];
    __shared__ float w[16];
    int x = blockIdx.x, tid = threadIdx.x;
    if (tid < 16) { gz[tid] = __expf(-INV2G2 * (float)(tid * tid)); w[tid] = W[tid]; }
    int i = x * 256 + tid;
    st[tid] = g_t1[i];
    __syncthreads();
    int y = tid >> 4, z = tid & 15;
    float4 sp = make_float4(0.f, 0.f, 0.f, 0.f);
    for (int zp = 0; zp < NZ; zp++) {
        int d = z - zp; if (d < 0) d = -d;
        float wt = gz[d];
        float4 v = st[y * 16 + zp];
        sp.x += wt * v.x; sp.y += wt * v.y; sp.z += wt * v.z; sp.w += wt * v.w;
    }
    // reduce bilateral partials
    float4 bl = make_float4(0.f, 0.f, 0.f, 0.f);
    #pragma unroll 8
    for (int c = 0; c < NCHUNK; c++) {
        float4 p = g_part[(size_t)c * N + i];
        bl.x += p.x; bl.y += p.y; bl.z += p.z; bl.w += p.w;
    }
    float2 m = g_m12[i];
    float4 qc;
    qc.x = m.x * bl.x + m.y * sp.x;
    qc.y = m.x * bl.y + m.y * sp.y;
    qc.z = m.x * bl.z + m.y * sp.z;
    qc.w = m.x * bl.w + m.y * sp.w;
    float4 l = g_lu[i];
    l.x -= w[0]  * qc.x + w[1]  * qc.y + w[2]  * qc.z + w[3]  * qc.w;
    l.y -= w[4]  * qc.x + w[5]  * qc.y + w[6]  * qc.z + w[7]  * qc.w;
    l.z -= w[8]  * qc.x + w[9]  * qc.y + w[10] * qc.z + w[11] * qc.w;
    l.w -= w[12] * qc.x + w[13] * qc.y + w[14] * qc.z + w[15] * qc.w;
    float4 q = softmax4(l);
    g_v1[i] = make_float4(q.x * m.x, q.y * m.x, q.z * m.x, q.w * m.x);
    g_v2[i] = make_float4(q.x * m.y, q.y * m.y, q.z * m.y, q.w * m.y);
    if (last) {
        out[i]         = q.x;
        out[N + i]     = q.y;
        out[2 * N + i] = q.z;
        out[3 * N + i] = q.w;
    }
}

extern "C" void kernel_launch(void* const* d_in, const int* in_sizes, int n_in,
                              void* d_out, int out_size) {
    const float* lu   = (const float*)d_in[0];
    const float* feat = (const float*)d_in[1];
    const float* comp = (const float*)d_in[2];
    float* out = (float*)d_out;

    p0_kernel<<<32, 256>>>(lu, feat);
    p2_kernel<<<1024, 256>>>();
    p1b_kernel<<<32, 256>>>();
    for (int it = 0; it < NUM_ITER; ++it) {
        g_kernel<<<dim3(4, NCHUNK), 256>>>();
        sxy_kernel<<<16, 512>>>();
        szs_kernel<<<32, 256>>>(comp, out, it == NUM_ITER - 1 ? 1 : 0);
    }
}

// round 4
// speedup vs baseline: 4.5514x; 1.2587x over previous
#include <cuda_runtime.h>
#include <cuda_fp16.h>
#include <cuda_fp8.h>

#define N      8192
#define NX     32
#define NY     16
#define NZ     16
#define NUM_ITER 5
#define INV2A2 0.02f   // 1/(2*ALPHA^2), ALPHA=5
#define INV2G2 0.02f   // 1/(2*GAMMA^2), GAMMA=5
#define INVB   0.2f    // 1/BETA, BETA=5
#define NCHUNK 128     // j-chunks in g
#define JT     64      // j per chunk

// Scratch (device globals; allocation-free per harness rules)
__device__ float4  g_pt[N];                    // u1, u2, g, 0
__device__ float   g_r1[N];                    // bilateral row sums (quantized-consistent)
__device__ float2  g_m12[N];                   // m1, m2
__device__ unsigned char g_B[(size_t)N * N];   // UNscaled bilateral matrix, 64MB fp8 e4m3
__device__ float4  g_lu[N];                    // logits interleaved [N][4]
__device__ float4  g_v1[N];                    // m1 ⊙ q
__device__ float4  g_v2[N];                    // m2 ⊙ q
__device__ float4  g_part[(size_t)NCHUNK * N]; // g partial sums [chunk][i][4]  (16MB)
__device__ float4  g_bl[N];                    // reduced bilateral filter output
__device__ float4  g_t1[N];                    // spatial tmp after x+y passes

__device__ __forceinline__ float4 softmax4(float4 l) {
    float m = fmaxf(fmaxf(l.x, l.y), fmaxf(l.z, l.w));
    float e0 = __expf(l.x - m), e1 = __expf(l.y - m);
    float e2 = __expf(l.z - m), e3 = __expf(l.w - m);
    float s = 1.0f / (e0 + e1 + e2 + e3);
    return make_float4(e0 * s, e1 * s, e2 * s, e3 * s);
}

__device__ __forceinline__ float2 de8x2(unsigned int s16) {
    __half2_raw hr = __nv_cvt_fp8x2_to_halfraw2((__nv_fp8x2_storage_t)s16, __NV_E4M3);
    __half2 h = *reinterpret_cast<__half2*>(&hr);
    return __half22float2(h);
}

// P0: per-point features + logit reorg
__global__ void p0_kernel(const float* __restrict__ lu, const float* __restrict__ feat) {
    int i = blockIdx.x * blockDim.x + threadIdx.x;
    if (i >= N) return;
    float u1 = feat[i] * INVB, u2 = feat[N + i] * INVB;
    float g = __expf(-0.5f * (u1 * u1 + u2 * u2));
    g_pt[i] = make_float4(u1, u2, g, 0.f);
    g_lu[i] = make_float4(lu[i], lu[N + i], lu[2 * N + i], lu[3 * N + i]);
}

// P2: materialize UNscaled bilateral B_ij = g_i g_j exp(u_i.u_j - D2/50) in fp8,
// row sums accumulated from the QUANTIZED values (bias-free normalization).
// Warp per row; lanes strided (conflict-free LDS); fp8 bytes staged through smem
// so global stores are one STG.64 per lane per tile.
__global__ void p2_kernel() {
    __shared__ float4 tile[256];
    __shared__ unsigned char pk[8][256];
    int tid = threadIdx.x;
    int warp = tid >> 5, lane = tid & 31;
    int i = blockIdx.x * 8 + warp;
    float4 pi = g_pt[i];
    int xi = i >> 8, yi = (i >> 4) & 15, zi = i & 15;
    float dz = (float)(zi - (lane & 15));
    float dzq = dz * dz;
    float dy0 = (float)(yi - (lane >> 4));
    unsigned char* row = g_B + (size_t)i * N;
    float rsum = 0.f;
    for (int jb = 0; jb < N; jb += 256) {
        __syncthreads();
        tile[tid] = g_pt[jb + tid];
        __syncthreads();
        int dx = xi - (jb >> 8);
        float basef = (float)(dx * dx) + dzq;
        #pragma unroll
        for (int k = 0; k < 8; k++) {
            int t = lane + 32 * k;
            float4 pj = tile[t];
            float dy = dy0 - 2.0f * (float)k;
            float D2f = fmaf(dy, dy, basef);
            float dot = fmaf(pi.x, pj.x, pi.y * pj.y);
            float v = pi.z * pj.z * __expf(fmaf(-INV2A2, D2f, dot));
            unsigned char b = (unsigned char)__nv_cvt_float_to_fp8(v, __NV_SATFINITE, __NV_E4M3);
            pk[warp][t] = b;
            __half_raw hr = __nv_cvt_fp8_to_halfraw(b, __NV_E4M3);
            rsum += __half2float(*reinterpret_cast<__half*>(&hr));
        }
        __syncwarp();
        uint2 w = *reinterpret_cast<uint2*>(&pk[warp][lane * 8]);
        *reinterpret_cast<uint2*>(row + jb + lane * 8) = w;
    }
    #pragma unroll
    for (int o = 16; o > 0; o >>= 1) rsum += __shfl_xor_sync(0xffffffffu, rsum, o);
    if (lane == 0) g_r1[i] = rsum;
}

// P1b: scales (bilateral from r1; spatial analytic separable) + initial scaled q
__global__ void p1b_kernel() {
    int i = blockIdx.x * blockDim.x + threadIdx.x;
    if (i >= N) return;
    int x = i >> 8, y = (i >> 4) & 15, z = i & 15;
    float Rx = 0.f, Ry = 0.f, Rz = 0.f;
    for (int t = 0; t < NX; t++) { int d = x - t; Rx += __expf(-INV2G2 * (float)(d * d)); }
    for (int t = 0; t < NY; t++) { int d = y - t; Ry += __expf(-INV2G2 * (float)(d * d)); }
    for (int t = 0; t < NZ; t++) { int d = z - t; Rz += __expf(-INV2G2 * (float)(d * d)); }
    float m1 = rsqrtf(g_r1[i]);
    float m2 = rsqrtf(Rx * Ry * Rz);
    g_m12[i] = make_float2(m1, m2);
    float4 q = softmax4(g_lu[i]);
    g_v1[i] = make_float4(q.x * m1, q.y * m1, q.z * m1, q.w * m1);
    g_v2[i] = make_float4(q.x * m2, q.y * m2, q.z * m2, q.w * m2);
}

// G: partial = B(cols) @ v1 over one j-chunk. B symmetric -> read rows as columns.
// grid (4, 128) x 256. Warp owns 256 consecutive i; lane loads uint2 = 8 fp8.
__global__ void g_kernel() {
    __shared__ float4 qsh[JT];
    int tid = threadIdx.x, warp = tid >> 5, lane = tid & 31;
    int jb = blockIdx.y * JT;
    if (tid < JT) qsh[tid] = g_v1[jb + tid];
    __syncthreads();
    int i0 = blockIdx.x * 2048 + warp * 256 + lane * 8;
    float4 a[8];
    #pragma unroll
    for (int k = 0; k < 8; k++) a[k] = make_float4(0.f, 0.f, 0.f, 0.f);
    const unsigned char* Bp = g_B + (size_t)jb * N + i0;
    #pragma unroll 8
    for (int jj = 0; jj < JT; jj++) {
        float4 q4 = qsh[jj];
        uint2 raw = *reinterpret_cast<const uint2*>(Bp + (size_t)jj * N);
        float2 m0 = de8x2(raw.x & 0xffffu);
        float2 m1 = de8x2(raw.x >> 16);
        float2 m2 = de8x2(raw.y & 0xffffu);
        float2 m3 = de8x2(raw.y >> 16);
        a[0].x += m0.x * q4.x; a[0].y += m0.x * q4.y; a[0].z += m0.x * q4.z; a[0].w += m0.x * q4.w;
        a[1].x += m0.y * q4.x; a[1].y += m0.y * q4.y; a[1].z += m0.y * q4.z; a[1].w += m0.y * q4.w;
        a[2].x += m1.x * q4.x; a[2].y += m1.x * q4.y; a[2].z += m1.x * q4.z; a[2].w += m1.x * q4.w;
        a[3].x += m1.y * q4.x; a[3].y += m1.y * q4.y; a[3].z += m1.y * q4.z; a[3].w += m1.y * q4.w;
        a[4].x += m2.x * q4.x; a[4].y += m2.x * q4.y; a[4].z += m2.x * q4.z; a[4].w += m2.x * q4.w;
        a[5].x += m2.y * q4.x; a[5].y += m2.y * q4.y; a[5].z += m2.y * q4.z; a[5].w += m2.y * q4.w;
        a[6].x += m3.x * q4.x; a[6].y += m3.x * q4.y; a[6].z += m3.x * q4.z; a[6].w += m3.x * q4.w;
        a[7].x += m3.y * q4.x; a[7].y += m3.y * q4.y; a[7].z += m3.y * q4.z; a[7].w += m3.y * q4.w;
    }
    float4* dst = g_part + (size_t)blockIdx.y * N + i0;
    #pragma unroll
    for (int k = 0; k < 8; k++) dst[k] = a[k];
}

// MID: fused (a) spatial x+y separable passes (blocks 0..15, one per z-slice) and
// (b) reduction of bilateral partials (blocks 16..79, 64 blocks x 512 threads).
__global__ void mid_kernel() {
    int bid = blockIdx.x, tid = threadIdx.x;
    if (bid < 16) {
        __shared__ float4 sin_[512];
        __shared__ float4 smid[512];
        __shared__ float gx[NX];
        int z = bid;
        if (tid < NX) gx[tid] = __expf(-INV2G2 * (float)(tid * tid));
        int x = tid >> 4, y = tid & 15;
        sin_[tid] = g_v2[x * 256 + y * 16 + z];
        __syncthreads();
        float4 acc = make_float4(0.f, 0.f, 0.f, 0.f);
        for (int xp = 0; xp < NX; xp++) {
            int d = x - xp; if (d < 0) d = -d;
            float w = gx[d];
            float4 v = sin_[xp * 16 + y];
            acc.x += w * v.x; acc.y += w * v.y; acc.z += w * v.z; acc.w += w * v.w;
        }
        smid[tid] = acc;
        __syncthreads();
        float4 acc2 = make_float4(0.f, 0.f, 0.f, 0.f);
        for (int yp = 0; yp < NY; yp++) {
            int d = y - yp; if (d < 0) d = -d;
            float w = gx[d];
            float4 v = smid[x * 16 + yp];
            acc2.x += w * v.x; acc2.y += w * v.y; acc2.z += w * v.z; acc2.w += w * v.w;
        }
        g_t1[x * 256 + y * 16 + z] = acc2;
    } else {
        // reduce partials: one float per thread, 64 blocks x 512 = 32768 = 4N
        int t = (bid - 16) * 512 + tid;
        const float* pp = reinterpret_cast<const float*>(g_part);
        float s = 0.f;
        #pragma unroll 16
        for (int c = 0; c < NCHUNK; c++) s += pp[(size_t)c * (N * 4) + t];
        reinterpret_cast<float*>(g_bl)[t] = s;
    }
}

// SZS: z-pass of spatial + combine with reduced bilateral + compat + softmax update.
__global__ void szs_kernel(const float* __restrict__ W, float* __restrict__ out, int last) {
    __shared__ float4 st[256];
    __shared__ float gz[NZ];
    __shared__ float w[16];
    int x = blockIdx.x, tid = threadIdx.x;
    if (tid < 16) { gz[tid] = __expf(-INV2G2 * (float)(tid * tid)); w[tid] = W[tid]; }
    int i = x * 256 + tid;
    st[tid] = g_t1[i];
    __syncthreads();
    int y = tid >> 4, z = tid & 15;
    float4 sp = make_float4(0.f, 0.f, 0.f, 0.f);
    for (int zp = 0; zp < NZ; zp++) {
        int d = z - zp; if (d < 0) d = -d;
        float wt = gz[d];
        float4 v = st[y * 16 + zp];
        sp.x += wt * v.x; sp.y += wt * v.y; sp.z += wt * v.z; sp.w += wt * v.w;
    }
    float4 bl = g_bl[i];
    float2 m = g_m12[i];
    float4 qc;
    qc.x = m.x * bl.x + m.y * sp.x;
    qc.y = m.x * bl.y + m.y * sp.y;
    qc.z = m.x * bl.z + m.y * sp.z;
    qc.w = m.x * bl.w + m.y * sp.w;
    float4 l = g_lu[i];
    l.x -= w[0]  * qc.x + w[1]  * qc.y + w[2]  * qc.z + w[3]  * qc.w;
    l.y -= w[4]  * qc.x + w[5]  * qc.y + w[6]  * qc.z + w[7]  * qc.w;
    l.z -= w[8]  * qc.x + w[9]  * qc.y + w[10] * qc.z + w[11] * qc.w;
    l.w -= w[12] * qc.x + w[13] * qc.y + w[14] * qc.z + w[15] * qc.w;
    float4 q = softmax4(l);
    g_v1[i] = make_float4(q.x * m.x, q.y * m.x, q.z * m.x, q.w * m.x);
    g_v2[i] = make_float4(q.x * m.y, q.y * m.y, q.z * m.y, q.w * m.y);
    if (last) {
        out[i]         = q.x;
        out[N + i]     = q.y;
        out[2 * N + i] = q.z;
        out[3 * N + i] = q.w;
    }
}

extern "C" void kernel_launch(void* const* d_in, const int* in_sizes, int n_in,
                              void* d_out, int out_size) {
    const float* lu   = (const float*)d_in[0];
    const float* feat = (const float*)d_in[1];
    const float* comp = (const float*)d_in[2];
    float* out = (float*)d_out;

    p0_kernel<<<32, 256>>>(lu, feat);
    p2_kernel<<<1024, 256>>>();
    p1b_kernel<<<32, 256>>>();
    for (int it = 0; it < NUM_ITER; ++it) {
        g_kernel<<<dim3(4, NCHUNK), 256>>>();
        mid_kernel<<<80, 512>>>();
        szs_kernel<<<32, 256>>>(comp, out, it == NUM_ITER - 1 ? 1 : 0);
    }
}

// round 5
// speedup vs baseline: 6.8581x; 1.5068x over previous
#include <cuda_runtime.h>

#define N      8192
#define NUM_ITER 5
#define INVB   0.2f    // 1/BETA
#define INV2S  0.02f   // 1/(2*5^2) shared spatial bandwidth (ALPHA == GAMMA == 5)
#define NF     36      // Taylor features, total degree <= 7
#define NFU    37      // + 1 spatial unit

__constant__ int FM[NF] = {0, 0,1, 0,1,2, 0,1,2,3, 0,1,2,3,4, 0,1,2,3,4,5, 0,1,2,3,4,5,6, 0,1,2,3,4,5,6,7};
__constant__ int FN[NF] = {0, 1,0, 2,1,0, 3,2,1,0, 4,3,2,1,0, 5,4,3,2,1,0, 6,5,4,3,2,1,0, 7,6,5,4,3,2,1,0};
__constant__ float FACT[8] = {1.f,1.f,2.f,6.f,24.f,120.f,720.f,5040.f};

// Scratch (device globals; allocation-free per harness rules)
__device__ float4 g_pt[N];          // u1, u2, g, 0
__device__ float4 g_lu[N];          // logits [N][4]
__device__ float2 g_m12[N];         // m1, m2
__device__ float4 g_wb[N];          // bilateral input vec  (g*m1*q ; mode0: g)
__device__ float4 g_ws[N];          // spatial  input vec  (m2*q  ; mode0: 1)
__device__ float4 g_F4[NFU * N];    // filtered maps after x+y pass, [unit][z*512 + x*16 + y]
__device__ float4 g_projp[5 * N];   // projection partials per feature-group
__device__ float4 g_projs[N];       // spatial filter output

__device__ __forceinline__ float4 softmax4(float4 l) {
    float m = fmaxf(fmaxf(l.x, l.y), fmaxf(l.z, l.w));
    float e0 = __expf(l.x - m), e1 = __expf(l.y - m);
    float e2 = __expf(l.z - m), e3 = __expf(l.w - m);
    float s = 1.0f / (e0 + e1 + e2 + e3);
    return make_float4(e0 * s, e1 * s, e2 * s, e3 * s);
}

// phi_{m,n}(u) = u1^m u2^n / sqrt(m! n!)   (u uniform per call site across warp)
__device__ __forceinline__ float phi_u(int u, float u1, float u2) {
    int m = FM[u], n = FN[u];
    float p = rsqrtf(FACT[m] * FACT[n]);
    for (int t = 0; t < m; t++) p *= u1;
    for (int t = 0; t < n; t++) p *= u2;
    return p;
}

// P0: per-point features + logit reorg + mode0 inputs
__global__ void p0_kernel(const float* __restrict__ lu, const float* __restrict__ feat) {
    int i = blockIdx.x * blockDim.x + threadIdx.x;
    if (i >= N) return;
    float u1 = feat[i] * INVB, u2 = feat[N + i] * INVB;
    float g = __expf(-0.5f * (u1 * u1 + u2 * u2));
    g_pt[i] = make_float4(u1, u2, g, 0.f);
    g_lu[i] = make_float4(lu[i], lu[N + i], lu[2 * N + i], lu[3 * N + i]);
    g_wb[i] = make_float4(g, g, g, g);          // mode0: norm pass input
    g_ws[i] = make_float4(1.f, 1.f, 1.f, 1.f);
}

// AB: expand to feature maps + separable x and y Gaussian passes, per z-slice.
// grid = 16 z-slices x 13 unit-groups (3 units each); 512 threads = (x,y) slice.
__global__ void ab_kernel() {
    __shared__ float4 sa[512];
    __shared__ float4 sb[512];
    __shared__ float Wd[32];
    int z = blockIdx.x & 15, mg = blockIdx.x >> 4;
    int tid = threadIdx.x;
    int x = tid >> 4, y = tid & 15;
    if (tid < 32) Wd[tid] = __expf(-INV2S * (float)(tid * tid));
    int i = x * 256 + y * 16 + z;
    float4 pt = g_pt[i];
    float4 wb = g_wb[i];
    float4 ws = g_ws[i];
    __syncthreads();
    int u0 = mg * 3, ue = min(NFU, u0 + 3);
    for (int u = u0; u < ue; u++) {
        float4 in;
        if (u < NF) {
            float p = phi_u(u, pt.x, pt.y);
            in = make_float4(p * wb.x, p * wb.y, p * wb.z, p * wb.w);
        } else {
            in = ws;
        }
        sa[tid] = in;
        __syncthreads();
        float4 a = make_float4(0.f, 0.f, 0.f, 0.f);
        #pragma unroll
        for (int xp = 0; xp < 32; xp++) {
            int d = x - xp; if (d < 0) d = -d;
            float w = Wd[d];
            float4 v = sa[xp * 16 + y];
            a.x += w * v.x; a.y += w * v.y; a.z += w * v.z; a.w += w * v.w;
        }
        sb[tid] = a;
        __syncthreads();
        float4 b = make_float4(0.f, 0.f, 0.f, 0.f);
        #pragma unroll
        for (int yp = 0; yp < 16; yp++) {
            int d = y - yp; if (d < 0) d = -d;
            float w = Wd[d];
            float4 v = sb[x * 16 + yp];
            b.x += w * v.x; b.y += w * v.y; b.z += w * v.z; b.w += w * v.w;
        }
        g_F4[u * N + z * 512 + tid] = b;
        __syncthreads();
    }
}

// CZ: z-pass + projection back through phi. grid = 32 x-slabs x 5 feature-groups
// (8 units each; last group 5 incl spatial). 256 threads = (y,z) of the slab.
__global__ void cz_kernel() {
    __shared__ float4 sm[2][256];
    __shared__ float Wd[16];
    int x = blockIdx.x & 31, fg = blockIdx.x >> 5;
    int tid = threadIdx.x;
    if (tid < 16) Wd[tid] = __expf(-INV2S * (float)(tid * tid));
    int y = tid >> 4, z = tid & 15;
    int i = x * 256 + y * 16 + z;
    float4 pt = g_pt[i];
    float4 proj = make_float4(0.f, 0.f, 0.f, 0.f);
    float4 sp   = make_float4(0.f, 0.f, 0.f, 0.f);
    int u0 = fg * 8, ue = min(NFU, u0 + 8);
    __syncthreads();
    for (int ur = u0; ur < ue; ur += 2) {
        // loader role: zl = tid>>4, yl = tid&15 -> sm[k][zl*16+yl] = sm[k][tid]
        sm[0][tid] = g_F4[ur * N + (tid >> 4) * 512 + x * 16 + (tid & 15)];
        if (ur + 1 < ue)
            sm[1][tid] = g_F4[(ur + 1) * N + (tid >> 4) * 512 + x * 16 + (tid & 15)];
        __syncthreads();
        #pragma unroll
        for (int k = 0; k < 2; k++) {
            int u = ur + k;
            if (u >= ue) break;
            float4 zf = make_float4(0.f, 0.f, 0.f, 0.f);
            #pragma unroll
            for (int zp = 0; zp < 16; zp++) {
                int d = z - zp; if (d < 0) d = -d;
                float w = Wd[d];
                float4 v = sm[k][zp * 16 + y];
                zf.x += w * v.x; zf.y += w * v.y; zf.z += w * v.z; zf.w += w * v.w;
            }
            if (u < NF) {
                float p = phi_u(u, pt.x, pt.y);
                proj.x += p * zf.x; proj.y += p * zf.y;
                proj.z += p * zf.z; proj.w += p * zf.w;
            } else {
                sp = zf;
            }
        }
        __syncthreads();
    }
    g_projp[fg * N + i] = proj;
    if (fg == 4) g_projs[i] = sp;
}

// F0: norm finalize — m1 from bilateral row sum, m2 from spatial row sum;
// initial q and scaled inputs for iteration 1.
__global__ void f0_kernel() {
    int i = blockIdx.x * blockDim.x + threadIdx.x;
    if (i >= N) return;
    float4 pb = make_float4(0.f, 0.f, 0.f, 0.f);
    #pragma unroll
    for (int fgi = 0; fgi < 5; fgi++) {
        float4 p = g_projp[fgi * N + i];
        pb.x += p.x; pb.y += p.y; pb.z += p.z; pb.w += p.w;
    }
    float4 sp = g_projs[i];
    float4 pt = g_pt[i];
    float m1 = rsqrtf(pt.z * pb.x);   // row sum of K1
    float m2 = rsqrtf(sp.x);          // row sum of K2
    g_m12[i] = make_float2(m1, m2);
    float4 q = softmax4(g_lu[i]);
    float c1 = pt.z * m1;
    g_wb[i] = make_float4(q.x * c1, q.y * c1, q.z * c1, q.w * c1);
    g_ws[i] = make_float4(q.x * m2, q.y * m2, q.z * m2, q.w * m2);
}

// F: combine bilateral + spatial, compatibility, softmax update; refresh inputs.
__global__ void f_kernel(const float* __restrict__ W, float* __restrict__ out, int last) {
    __shared__ float w[16];
    int tid = threadIdx.x;
    if (tid < 16) w[tid] = W[tid];
    int i = blockIdx.x * blockDim.x + tid;
    float4 pb = make_float4(0.f, 0.f, 0.f, 0.f);
    #pragma unroll
    for (int fgi = 0; fgi < 5; fgi++) {
        float4 p = g_projp[fgi * N + i];
        pb.x += p.x; pb.y += p.y; pb.z += p.z; pb.w += p.w;
    }
    float4 sp = g_projs[i];
    float4 pt = g_pt[i];
    float2 m = g_m12[i];
    __syncthreads();
    float c1 = pt.z * m.x;
    float4 qc;
    qc.x = c1 * pb.x + m.y * sp.x;
    qc.y = c1 * pb.y + m.y * sp.y;
    qc.z = c1 * pb.z + m.y * sp.z;
    qc.w = c1 * pb.w + m.y * sp.w;
    float4 l = g_lu[i];
    l.x -= w[0]  * qc.x + w[1]  * qc.y + w[2]  * qc.z + w[3]  * qc.w;
    l.y -= w[4]  * qc.x + w[5]  * qc.y + w[6]  * qc.z + w[7]  * qc.w;
    l.z -= w[8]  * qc.x + w[9]  * qc.y + w[10] * qc.z + w[11] * qc.w;
    l.w -= w[12] * qc.x + w[13] * qc.y + w[14] * qc.z + w[15] * qc.w;
    float4 q = softmax4(l);
    g_wb[i] = make_float4(q.x * c1, q.y * c1, q.z * c1, q.w * c1);
    g_ws[i] = make_float4(q.x * m.y, q.y * m.y, q.z * m.y, q.w * m.y);
    if (last) {
        out[i]         = q.x;
        out[N + i]     = q.y;
        out[2 * N + i] = q.z;
        out[3 * N + i] = q.w;
    }
}

extern "C" void kernel_launch(void* const* d_in, const int* in_sizes, int n_in,
                              void* d_out, int out_size) {
    const float* lu   = (const float*)d_in[0];
    const float* feat = (const float*)d_in[1];
    const float* comp = (const float*)d_in[2];
    float* out = (float*)d_out;

    p0_kernel<<<32, 256>>>(lu, feat);
    ab_kernel<<<16 * 13, 512>>>();      // norm pass (mode0 inputs from p0)
    cz_kernel<<<32 * 5, 256>>>();
    f0_kernel<<<32, 256>>>();
    for (int it = 0; it < NUM_ITER; ++it) {
        ab_kernel<<<16 * 13, 512>>>();
        cz_kernel<<<32 * 5, 256>>>();
        f_kernel<<<32, 256>>>(comp, out, it == NUM_ITER - 1 ? 1 : 0);
    }
}

// round 6
// speedup vs baseline: 7.3655x; 1.0740x over previous
#include <cuda_runtime.h>

#define NPTS   8192
#define NUM_ITER 5
#define INVB   0.2f    // 1/BETA
#define INV2S  0.02f   // 1/(2*5^2) shared spatial bandwidth (ALPHA == GAMMA == 5)
#define NF     36      // Taylor features, total degree <= 7
#define NFU    37      // + 1 spatial unit
#define NBLK   148
#define NTHR   512

__constant__ int FM[NF] = {0, 0,1, 0,1,2, 0,1,2,3, 0,1,2,3,4, 0,1,2,3,4,5, 0,1,2,3,4,5,6, 0,1,2,3,4,5,6,7};
__constant__ int FN[NF] = {0, 1,0, 2,1,0, 3,2,1,0, 4,3,2,1,0, 5,4,3,2,1,0, 6,5,4,3,2,1,0, 7,6,5,4,3,2,1,0};
__constant__ float FACT[8] = {1.f,1.f,2.f,6.f,24.f,120.f,720.f,5040.f};

// Device scratch (allocation-free per harness rules)
__device__ float4 g_pt[NPTS];          // u1, u2, g, 0
__device__ float4 g_lu[NPTS];          // logits [N][4]
__device__ float2 g_m12[NPTS];         // m1, m2
__device__ float4 g_wb[NPTS];          // bilateral input (g*m1*q ; norm pass: g)
__device__ float4 g_ws[NPTS];          // spatial input  (m2*q   ; norm pass: 1)
__device__ float4 g_F4[NFU * NPTS];    // x+y-filtered maps, [u][z*512 + x*16 + y]
__device__ unsigned int g_barc;        // grid barrier arrival count
__device__ volatile unsigned int g_barg; // grid barrier generation

__device__ __forceinline__ void gsync(unsigned int* gen) {
    __syncthreads();
    if (threadIdx.x == 0) {
        __threadfence();
        unsigned int target = *gen + 1;
        if (atomicAdd(&g_barc, 1u) == NBLK - 1) {
            g_barc = 0;
            __threadfence();
            g_barg = target;
        } else {
            while (g_barg != target) __nanosleep(64);
            __threadfence();
        }
        *gen = target;
    }
    __syncthreads();
}

__device__ __forceinline__ float4 softmax4(float4 l) {
    float m = fmaxf(fmaxf(l.x, l.y), fmaxf(l.z, l.w));
    float e0 = __expf(l.x - m), e1 = __expf(l.y - m);
    float e2 = __expf(l.z - m), e3 = __expf(l.w - m);
    float s = 1.0f / (e0 + e1 + e2 + e3);
    return make_float4(e0 * s, e1 * s, e2 * s, e3 * s);
}

__device__ __forceinline__ float phi_u(int u, float u1, float u2) {
    int m = FM[u], n = FN[u];
    float p = rsqrtf(FACT[m] * FACT[n]);
    for (int t = 0; t < m; t++) p *= u1;
    for (int t = 0; t < n; t++) p *= u2;
    return p;
}

__shared__ union {
    struct { float4 sa[512]; float4 sb[512]; } ab;
    struct { float4 tile[512]; float4 red[512]; float4 ssp[64]; } cz;
} sh;
__shared__ float Wd[32];
__shared__ float wc[16];

// AB phase: expand unit u, filter along x then y for slice z. 592 tasks = NBLK*4.
__device__ __forceinline__ void ab_phase(int b, int t) {
    int x = t >> 4, y = t & 15;
    #pragma unroll
    for (int r = 0; r < 4; r++) {
        int task = b + NBLK * r;         // 0..591
        int u = task >> 4, z = task & 15;
        int i = x * 256 + y * 16 + z;
        float4 in;
        if (u < NF) {
            float4 pt = g_pt[i];
            float4 wb = g_wb[i];
            float p = phi_u(u, pt.x, pt.y);
            in = make_float4(p * wb.x, p * wb.y, p * wb.z, p * wb.w);
        } else {
            in = g_ws[i];
        }
        sh.ab.sa[t] = in;
        __syncthreads();
        float4 a = make_float4(0.f, 0.f, 0.f, 0.f);
        #pragma unroll
        for (int xp = 0; xp < 32; xp++) {
            int d = x - xp; if (d < 0) d = -d;
            float w = Wd[d];
            float4 v = sh.ab.sa[xp * 16 + y];
            a.x += w * v.x; a.y += w * v.y; a.z += w * v.z; a.w += w * v.w;
        }
        sh.ab.sb[t] = a;
        __syncthreads();
        float4 bb = make_float4(0.f, 0.f, 0.f, 0.f);
        #pragma unroll
        for (int yp = 0; yp < 16; yp++) {
            int d = y - yp; if (d < 0) d = -d;
            float w = Wd[d];
            float4 v = sh.ab.sb[x * 16 + yp];
            bb.x += w * v.x; bb.y += w * v.y; bb.z += w * v.z; bb.w += w * v.w;
        }
        g_F4[u * NPTS + z * 512 + t] = bb;
        __syncthreads();
    }
}

// CZF phase: z-filter + projection + fused F update. Blocks 0..127 active;
// block = (x-slab, y-quarter) owns 64 points across ALL units (8 per round).
__device__ __forceinline__ void czf_phase(int b, int t, int mode, int last,
                                          float* __restrict__ out) {
    if (b >= 128) return;
    int x = b & 31, yq = b >> 5;
    int ul = t >> 6, p = t & 63;
    int yl = p >> 4, zl = p & 15;
    int y = yq * 4 + yl, z = zl;
    int i = x * 256 + y * 16 + z;
    float4 pt = g_pt[i];
    float4 acc = make_float4(0.f, 0.f, 0.f, 0.f);
    for (int ur = 0; ur < 40; ur += 8) {
        int u = ur + ul;
        if (u < NFU)
            sh.cz.tile[t] = g_F4[u * NPTS + zl * 512 + x * 16 + y];
        __syncthreads();
        if (u < NFU) {
            float4 zf = make_float4(0.f, 0.f, 0.f, 0.f);
            #pragma unroll
            for (int zp = 0; zp < 16; zp++) {
                int d = z - zp; if (d < 0) d = -d;
                float w = Wd[d];
                float4 v = sh.cz.tile[ul * 64 + yl * 16 + zp];
                zf.x += w * v.x; zf.y += w * v.y; zf.z += w * v.z; zf.w += w * v.w;
            }
            if (u < NF) {
                float ph = phi_u(u, pt.x, pt.y);
                acc.x += ph * zf.x; acc.y += ph * zf.y;
                acc.z += ph * zf.z; acc.w += ph * zf.w;
            } else {
                sh.cz.ssp[p] = zf;   // spatial unit (u == 36)
            }
        }
        __syncthreads();
    }
    sh.cz.red[t] = acc;
    __syncthreads();
    if (t < 256) { float4 o = sh.cz.red[t + 256];
        sh.cz.red[t].x += o.x; sh.cz.red[t].y += o.y; sh.cz.red[t].z += o.z; sh.cz.red[t].w += o.w; }
    __syncthreads();
    if (t < 128) { float4 o = sh.cz.red[t + 128];
        sh.cz.red[t].x += o.x; sh.cz.red[t].y += o.y; sh.cz.red[t].z += o.z; sh.cz.red[t].w += o.w; }
    __syncthreads();
    if (t < 64) {
        float4 proj = sh.cz.red[t];
        float4 o = sh.cz.red[t + 64];
        proj.x += o.x; proj.y += o.y; proj.z += o.z; proj.w += o.w;
        float4 sp = sh.cz.ssp[t];
        int yy = yq * 4 + (t >> 4), zz = t & 15;
        int ii = x * 256 + yy * 16 + zz;
        float4 ptl = g_pt[ii];
        if (mode == 0) {
            float m1 = rsqrtf(ptl.z * proj.x);   // K1 row sum
            float m2 = rsqrtf(sp.x);             // K2 row sum
            g_m12[ii] = make_float2(m1, m2);
            float4 q = softmax4(g_lu[ii]);
            float c1 = ptl.z * m1;
            g_wb[ii] = make_float4(q.x * c1, q.y * c1, q.z * c1, q.w * c1);
            g_ws[ii] = make_float4(q.x * m2, q.y * m2, q.z * m2, q.w * m2);
        } else {
            float2 m = g_m12[ii];
            float c1 = ptl.z * m.x;
            float4 qc;
            qc.x = c1 * proj.x + m.y * sp.x;
            qc.y = c1 * proj.y + m.y * sp.y;
            qc.z = c1 * proj.z + m.y * sp.z;
            qc.w = c1 * proj.w + m.y * sp.w;
            float4 l = g_lu[ii];
            l.x -= wc[0]  * qc.x + wc[1]  * qc.y + wc[2]  * qc.z + wc[3]  * qc.w;
            l.y -= wc[4]  * qc.x + wc[5]  * qc.y + wc[6]  * qc.z + wc[7]  * qc.w;
            l.z -= wc[8]  * qc.x + wc[9]  * qc.y + wc[10] * qc.z + wc[11] * qc.w;
            l.w -= wc[12] * qc.x + wc[13] * qc.y + wc[14] * qc.z + wc[15] * qc.w;
            float4 q = softmax4(l);
            g_wb[ii] = make_float4(q.x * c1, q.y * c1, q.z * c1, q.w * c1);
            g_ws[ii] = make_float4(q.x * m.y, q.y * m.y, q.z * m.y, q.w * m.y);
            if (last) {
                out[ii]            = q.x;
                out[NPTS + ii]     = q.y;
                out[2 * NPTS + ii] = q.z;
                out[3 * NPTS + ii] = q.w;
            }
        }
    }
}

__global__ void __launch_bounds__(NTHR)
crf_kernel(const float* __restrict__ lu, const float* __restrict__ feat,
           const float* __restrict__ W, float* __restrict__ out) {
    int b = blockIdx.x, t = threadIdx.x;
    if (t < 32) Wd[t] = __expf(-INV2S * (float)(t * t));
    if (t < 16) wc[t] = W[t];
    unsigned int gen = g_barg;

    // P0: per-point features + logit reorg + norm-pass inputs (blocks 0..15)
    if (b < 16) {
        int i = b * 512 + t;
        float u1 = feat[i] * INVB, u2 = feat[NPTS + i] * INVB;
        float g = __expf(-0.5f * (u1 * u1 + u2 * u2));
        g_pt[i] = make_float4(u1, u2, g, 0.f);
        g_lu[i] = make_float4(lu[i], lu[NPTS + i], lu[2 * NPTS + i], lu[3 * NPTS + i]);
        g_wb[i] = make_float4(g, g, g, g);
        g_ws[i] = make_float4(1.f, 1.f, 1.f, 1.f);
    }
    gsync(&gen);

    // Norm pass
    ab_phase(b, t);
    gsync(&gen);
    czf_phase(b, t, 0, 0, out);
    gsync(&gen);

    // Mean-field iterations
    for (int it = 0; it < NUM_ITER; it++) {
        ab_phase(b, t);
        gsync(&gen);
        czf_phase(b, t, 1, it == NUM_ITER - 1 ? 1 : 0, out);
        if (it != NUM_ITER - 1) gsync(&gen);
    }
}

extern "C" void kernel_launch(void* const* d_in, const int* in_sizes, int n_in,
                              void* d_out, int out_size) {
    const float* lu   = (const float*)d_in[0];
    const float* feat = (const float*)d_in[1];
    const float* comp = (const float*)d_in[2];
    float* out = (float*)d_out;
    crf_kernel<<<NBLK, NTHR>>>(lu, feat, comp, out);
}

// round 7
// speedup vs baseline: 8.6681x; 1.1769x over previous
#include <cuda_runtime.h>

#define NPTS   8192
#define NUM_ITER 5
#define INVB   0.2f    // 1/BETA
#define INV2S  0.02f   // 1/(2*5^2) shared spatial bandwidth (ALPHA == GAMMA == 5)
#define NF     28      // Taylor features, total degree <= 6
#define NFU    29      // + 1 spatial unit
#define NBLK   296     // 2 blocks/SM x 148 SMs -> all co-resident
#define NTHR   256
#define NABT   (NFU * 16)   // 464 AB tasks

__constant__ int FM[NF] = {0, 0,1, 0,1,2, 0,1,2,3, 0,1,2,3,4, 0,1,2,3,4,5, 0,1,2,3,4,5,6};
__constant__ int FN[NF] = {0, 1,0, 2,1,0, 3,2,1,0, 4,3,2,1,0, 5,4,3,2,1,0, 6,5,4,3,2,1,0};
__constant__ float FACT[7] = {1.f,1.f,2.f,6.f,24.f,120.f,720.f};

// Device scratch (allocation-free per harness rules)
__device__ float4 g_pt[NPTS];          // u1, u2, g, 0
__device__ float4 g_lu[NPTS];          // logits [N][4]
__device__ float2 g_m12[NPTS];         // m1, m2
__device__ float4 g_wb[NPTS];          // bilateral input (g*m1*q ; norm pass: g)
__device__ float4 g_ws[NPTS];          // spatial input  (m2*q   ; norm pass: 1)
__device__ float4 g_F4[NFU * NPTS];    // x+y-filtered maps, [u][z*512 + x*16 + y]
__device__ unsigned int g_barc;        // grid barrier arrival count
__device__ volatile unsigned int g_barg; // grid barrier generation

__device__ __forceinline__ void gsync(unsigned int* gen) {
    __syncthreads();
    if (threadIdx.x == 0) {
        __threadfence();
        unsigned int target = *gen + 1;
        if (atomicAdd(&g_barc, 1u) == NBLK - 1) {
            g_barc = 0;
            __threadfence();
            g_barg = target;
        } else {
            while (g_barg != target) __nanosleep(32);
            __threadfence();
        }
        *gen = target;
    }
    __syncthreads();
}

__device__ __forceinline__ float4 softmax4(float4 l) {
    float m = fmaxf(fmaxf(l.x, l.y), fmaxf(l.z, l.w));
    float e0 = __expf(l.x - m), e1 = __expf(l.y - m);
    float e2 = __expf(l.z - m), e3 = __expf(l.w - m);
    float s = 1.0f / (e0 + e1 + e2 + e3);
    return make_float4(e0 * s, e1 * s, e2 * s, e3 * s);
}

__device__ __forceinline__ float phi_u(int u, float u1, float u2) {
    int m = FM[u], n = FN[u];
    float p = rsqrtf(FACT[m] * FACT[n]);
    for (int t = 0; t < m; t++) p *= u1;
    for (int t = 0; t < n; t++) p *= u2;
    return p;
}

__shared__ union {
    struct { float4 sa[512]; float4 sb[512]; } ab;
    struct { float4 tile[256]; float4 red[256]; float4 ssp[32]; } cz;
} sh;
__shared__ float Wd[32];
__shared__ float wc[16];

// AB phase: expand unit u, x-filter, y-filter for slice z. 464 tasks, <=2 rounds.
__device__ __forceinline__ void ab_phase(int b, int t) {
    for (int r = 0; r < 2; r++) {
        int task = b + NBLK * r;
        if (task < NABT) {
            int u = task >> 4, z = task & 15;
            #pragma unroll
            for (int h = 0; h < 2; h++) {
                int p = t + 256 * h;
                int x = p >> 4, y = p & 15;
                int i = x * 256 + y * 16 + z;
                float4 in;
                if (u < NF) {
                    float4 pt = g_pt[i];
                    float4 wb = g_wb[i];
                    float ph = phi_u(u, pt.x, pt.y);
                    in = make_float4(ph * wb.x, ph * wb.y, ph * wb.z, ph * wb.w);
                } else {
                    in = g_ws[i];
                }
                sh.ab.sa[p] = in;
            }
            __syncthreads();
            #pragma unroll
            for (int h = 0; h < 2; h++) {
                int p = t + 256 * h;
                int x = p >> 4, y = p & 15;
                float4 a = make_float4(0.f, 0.f, 0.f, 0.f);
                #pragma unroll
                for (int xp = 0; xp < 32; xp++) {
                    int d = x - xp; if (d < 0) d = -d;
                    float w = Wd[d];
                    float4 v = sh.ab.sa[xp * 16 + y];
                    a.x += w * v.x; a.y += w * v.y; a.z += w * v.z; a.w += w * v.w;
                }
                sh.ab.sb[p] = a;
            }
            __syncthreads();
            #pragma unroll
            for (int h = 0; h < 2; h++) {
                int p = t + 256 * h;
                int x = p >> 4, y = p & 15;
                float4 bb = make_float4(0.f, 0.f, 0.f, 0.f);
                #pragma unroll
                for (int yp = 0; yp < 16; yp++) {
                    int d = y - yp; if (d < 0) d = -d;
                    float w = Wd[d];
                    float4 v = sh.ab.sb[x * 16 + yp];
                    bb.x += w * v.x; bb.y += w * v.y; bb.z += w * v.z; bb.w += w * v.w;
                }
                g_F4[u * NPTS + z * 512 + p] = bb;
            }
            __syncthreads();
        }
    }
}

// CZF phase: z-filter + projection + fused F update. Blocks 0..255 active;
// block = (x, y-pair) owns 32 points across all units (8 units per round).
__device__ __forceinline__ void czf_phase(int b, int t, int mode, int last,
                                          float* __restrict__ out) {
    if (b >= 256) return;
    int x = b >> 3, y0 = (b & 7) * 2;
    int ul = t >> 5, p = t & 31;
    int yl = p >> 4, zl = p & 15;
    int y = y0 + yl, z = zl;
    int i = x * 256 + y * 16 + z;
    float4 pt = g_pt[i];
    float4 acc = make_float4(0.f, 0.f, 0.f, 0.f);
    for (int ur = 0; ur < 32; ur += 8) {
        int u = ur + ul;
        if (u < NFU)
            sh.cz.tile[t] = g_F4[u * NPTS + zl * 512 + x * 16 + y];
        __syncthreads();
        if (u < NFU) {
            float4 zf = make_float4(0.f, 0.f, 0.f, 0.f);
            #pragma unroll
            for (int zp = 0; zp < 16; zp++) {
                int d = z - zp; if (d < 0) d = -d;
                float w = Wd[d];
                float4 v = sh.cz.tile[ul * 32 + yl * 16 + zp];
                zf.x += w * v.x; zf.y += w * v.y; zf.z += w * v.z; zf.w += w * v.w;
            }
            if (u < NF) {
                float ph = phi_u(u, pt.x, pt.y);
                acc.x += ph * zf.x; acc.y += ph * zf.y;
                acc.z += ph * zf.z; acc.w += ph * zf.w;
            } else {
                sh.cz.ssp[p] = zf;   // spatial unit (u == NF)
            }
        }
        __syncthreads();
    }
    sh.cz.red[t] = acc;
    __syncthreads();
    if (t < 128) { float4 o = sh.cz.red[t + 128];
        sh.cz.red[t].x += o.x; sh.cz.red[t].y += o.y; sh.cz.red[t].z += o.z; sh.cz.red[t].w += o.w; }
    __syncthreads();
    if (t < 64) { float4 o = sh.cz.red[t + 64];
        sh.cz.red[t].x += o.x; sh.cz.red[t].y += o.y; sh.cz.red[t].z += o.z; sh.cz.red[t].w += o.w; }
    __syncthreads();
    if (t < 32) {
        float4 proj = sh.cz.red[t];
        float4 o = sh.cz.red[t + 32];
        proj.x += o.x; proj.y += o.y; proj.z += o.z; proj.w += o.w;
        float4 sp = sh.cz.ssp[t];
        int yy = y0 + (t >> 4), zz = t & 15;
        int ii = x * 256 + yy * 16 + zz;
        float4 ptl = g_pt[ii];
        if (mode == 0) {
            float m1 = rsqrtf(ptl.z * proj.x);   // K1 row sum
            float m2 = rsqrtf(sp.x);             // K2 row sum
            g_m12[ii] = make_float2(m1, m2);
            float4 q = softmax4(g_lu[ii]);
            float c1 = ptl.z * m1;
            g_wb[ii] = make_float4(q.x * c1, q.y * c1, q.z * c1, q.w * c1);
            g_ws[ii] = make_float4(q.x * m2, q.y * m2, q.z * m2, q.w * m2);
        } else {
            float2 m = g_m12[ii];
            float c1 = ptl.z * m.x;
            float4 qc;
            qc.x = c1 * proj.x + m.y * sp.x;
            qc.y = c1 * proj.y + m.y * sp.y;
            qc.z = c1 * proj.z + m.y * sp.z;
            qc.w = c1 * proj.w + m.y * sp.w;
            float4 l = g_lu[ii];
            l.x -= wc[0]  * qc.x + wc[1]  * qc.y + wc[2]  * qc.z + wc[3]  * qc.w;
            l.y -= wc[4]  * qc.x + wc[5]  * qc.y + wc[6]  * qc.z + wc[7]  * qc.w;
            l.z -= wc[8]  * qc.x + wc[9]  * qc.y + wc[10] * qc.z + wc[11] * qc.w;
            l.w -= wc[12] * qc.x + wc[13] * qc.y + wc[14] * qc.z + wc[15] * qc.w;
            float4 q = softmax4(l);
            g_wb[ii] = make_float4(q.x * c1, q.y * c1, q.z * c1, q.w * c1);
            g_ws[ii] = make_float4(q.x * m.y, q.y * m.y, q.z * m.y, q.w * m.y);
            if (last) {
                out[ii]            = q.x;
                out[NPTS + ii]     = q.y;
                out[2 * NPTS + ii] = q.z;
                out[3 * NPTS + ii] = q.w;
            }
        }
    }
}

__global__ void __launch_bounds__(NTHR, 2)
crf_kernel(const float* __restrict__ lu, const float* __restrict__ feat,
           const float* __restrict__ W, float* __restrict__ out) {
    int b = blockIdx.x, t = threadIdx.x;
    if (t < 32) Wd[t] = __expf(-INV2S * (float)(t * t));
    if (t < 16) wc[t] = W[t];
    unsigned int gen = g_barg;

    // P0: per-point features + logit reorg + norm-pass inputs (blocks 0..31)
    if (b < 32) {
        int i = b * 256 + t;
        float u1 = feat[i] * INVB, u2 = feat[NPTS + i] * INVB;
        float g = __expf(-0.5f * (u1 * u1 + u2 * u2));
        g_pt[i] = make_float4(u1, u2, g, 0.f);
        g_lu[i] = make_float4(lu[i], lu[NPTS + i], lu[2 * NPTS + i], lu[3 * NPTS + i]);
        g_wb[i] = make_float4(g, g, g, g);
        g_ws[i] = make_float4(1.f, 1.f, 1.f, 1.f);
    }
    gsync(&gen);

    // Norm pass
    ab_phase(b, t);
    gsync(&gen);
    czf_phase(b, t, 0, 0, out);
    gsync(&gen);

    // Mean-field iterations
    for (int it = 0; it < NUM_ITER; it++) {
        ab_phase(b, t);
        gsync(&gen);
        czf_phase(b, t, 1, it == NUM_ITER - 1 ? 1 : 0, out);
        if (it != NUM_ITER - 1) gsync(&gen);
    }
}

extern "C" void kernel_launch(void* const* d_in, const int* in_sizes, int n_in,
                              void* d_out, int out_size) {
    const float* lu   = (const float*)d_in[0];
    const float* feat = (const float*)d_in[1];
    const float* comp = (const float*)d_in[2];
    float* out = (float*)d_out;
    crf_kernel<<<NBLK, NTHR>>>(lu, feat, comp, out);
}